// round 1
// baseline (speedup 1.0000x reference)
#include <cuda_runtime.h>

#define FEAT_DIM 128
#define WARPS_PER_BLOCK 8
#define THREADS_PER_BLOCK (WARPS_PER_BLOCK * 32)
#define ATOMS_PER_WARP 128

__global__ void zero_out_kernel(float* out, int n) {
    int i = blockIdx.x * blockDim.x + threadIdx.x;
    if (i < n) out[i] = 0.0f;
}

__launch_bounds__(THREADS_PER_BLOCK)
__global__ void atomwise_readout_kernel(const float4* __restrict__ f4,
                                        const int* __restrict__ seg,
                                        const float* __restrict__ w,
                                        float* __restrict__ out,
                                        int n_atoms) {
    const int lane = threadIdx.x & 31;
    const int warp_global =
        blockIdx.x * WARPS_PER_BLOCK + (threadIdx.x >> 5);

    long long start = (long long)warp_global * ATOMS_PER_WARP;
    if (start >= n_atoms) return;
    long long end = start + ATOMS_PER_WARP;
    if (end > n_atoms) end = n_atoms;

    // Each lane owns 4 contiguous weight values (lane*4 .. lane*4+3)
    const float4 wv = reinterpret_cast<const float4*>(w)[lane];

    int   cur_seg = seg[start];
    float acc     = 0.0f;

    long long a = start;

    // ---- 4-atom unrolled main loop: 4 independent shuffle-reduce chains ----
    for (; a + 4 <= end; a += 4) {
        float4 v0 = f4[(a + 0) * 32 + lane];
        float4 v1 = f4[(a + 1) * 32 + lane];
        float4 v2 = f4[(a + 2) * 32 + lane];
        float4 v3 = f4[(a + 3) * 32 + lane];

        float s0 = fmaf(v0.x, wv.x, fmaf(v0.y, wv.y, fmaf(v0.z, wv.z, v0.w * wv.w)));
        float s1 = fmaf(v1.x, wv.x, fmaf(v1.y, wv.y, fmaf(v1.z, wv.z, v1.w * wv.w)));
        float s2 = fmaf(v2.x, wv.x, fmaf(v2.y, wv.y, fmaf(v2.z, wv.z, v2.w * wv.w)));
        float s3 = fmaf(v3.x, wv.x, fmaf(v3.y, wv.y, fmaf(v3.z, wv.z, v3.w * wv.w)));

        #pragma unroll
        for (int off = 16; off > 0; off >>= 1) {
            s0 += __shfl_xor_sync(0xFFFFFFFFu, s0, off);
            s1 += __shfl_xor_sync(0xFFFFFFFFu, s1, off);
            s2 += __shfl_xor_sync(0xFFFFFFFFu, s2, off);
            s3 += __shfl_xor_sync(0xFFFFFFFFu, s3, off);
        }

        int g0 = seg[a + 0];
        int g1 = seg[a + 1];
        int g2 = seg[a + 2];
        int g3 = seg[a + 3];

        // Sorted segment ids: run-length accumulate, flush on change.
        if (g0 != cur_seg) { if (lane == 0) atomicAdd(&out[cur_seg], acc); acc = 0.0f; cur_seg = g0; }
        acc += s0;
        if (g1 != cur_seg) { if (lane == 0) atomicAdd(&out[cur_seg], acc); acc = 0.0f; cur_seg = g1; }
        acc += s1;
        if (g2 != cur_seg) { if (lane == 0) atomicAdd(&out[cur_seg], acc); acc = 0.0f; cur_seg = g2; }
        acc += s2;
        if (g3 != cur_seg) { if (lane == 0) atomicAdd(&out[cur_seg], acc); acc = 0.0f; cur_seg = g3; }
        acc += s3;
    }

    // ---- tail ----
    for (; a < end; a++) {
        float4 v = f4[a * 32 + lane];
        float s = fmaf(v.x, wv.x, fmaf(v.y, wv.y, fmaf(v.z, wv.z, v.w * wv.w)));
        #pragma unroll
        for (int off = 16; off > 0; off >>= 1)
            s += __shfl_xor_sync(0xFFFFFFFFu, s, off);
        int g = seg[a];
        if (g != cur_seg) { if (lane == 0) atomicAdd(&out[cur_seg], acc); acc = 0.0f; cur_seg = g; }
        acc += s;
    }

    if (lane == 0) atomicAdd(&out[cur_seg], acc);
}

extern "C" void kernel_launch(void* const* d_in, const int* in_sizes, int n_in,
                              void* d_out, int out_size) {
    // metadata order: f [n_atoms*128 f32], segment_ids [n_atoms i32],
    //                 (n_graphs scalar, maybe), w_e [128 f32] (last input)
    const float* f   = (const float*)d_in[0];
    const int*   seg = (const int*)d_in[1];
    const float* w   = (const float*)d_in[n_in - 1];  // w_e is last (128 elems)

    const int n_atoms = in_sizes[1];  // segment_ids element count
    float* out = (float*)d_out;

    // d_out is poisoned — zero it first.
    {
        int threads = 256;
        int blocks  = (out_size + threads - 1) / threads;
        zero_out_kernel<<<blocks, threads>>>(out, out_size);
    }

    const int total_warps = (n_atoms + ATOMS_PER_WARP - 1) / ATOMS_PER_WARP;
    const int blocks = (total_warps + WARPS_PER_BLOCK - 1) / WARPS_PER_BLOCK;

    atomwise_readout_kernel<<<blocks, THREADS_PER_BLOCK>>>(
        reinterpret_cast<const float4*>(f), seg, w, out, n_atoms);
}

// round 2
// speedup vs baseline: 1.0229x; 1.0229x over previous
#include <cuda_runtime.h>

#define WARPS_PER_BLOCK 8
#define THREADS_PER_BLOCK (WARPS_PER_BLOCK * 32)
#define NUM_BLOCKS 912   // 152 SMs * 6 resident blocks -> exactly one wave

__global__ void zero_out_kernel(float* out, int n) {
    int i = blockIdx.x * blockDim.x + threadIdx.x;
    if (i < n) out[i] = 0.0f;
}

// Warp-reduce per-lane accumulator and atomically flush to out[seg_id].
__device__ __forceinline__ void flush_seg(float& acc, int seg_id, int lane,
                                          float* __restrict__ out) {
    float s = acc;
    #pragma unroll
    for (int off = 16; off > 0; off >>= 1)
        s += __shfl_xor_sync(0xFFFFFFFFu, s, off);
    if (lane == 0) atomicAdd(&out[seg_id], s);
    acc = 0.0f;
}

__launch_bounds__(THREADS_PER_BLOCK)
__global__ void atomwise_readout_kernel(const float4* __restrict__ f4,
                                        const int* __restrict__ seg,
                                        const float* __restrict__ w,
                                        float* __restrict__ out,
                                        int n_atoms, int chunk) {
    const int lane = threadIdx.x & 31;
    const int warp_global = blockIdx.x * WARPS_PER_BLOCK + (threadIdx.x >> 5);

    long long start = (long long)warp_global * chunk;   // chunk is 4-aligned
    if (start >= n_atoms) return;
    long long end = start + chunk;
    if (end > n_atoms) end = n_atoms;

    const float4 wv = reinterpret_cast<const float4*>(w)[lane];

    int   cur_seg = seg[start];
    float acc     = 0.0f;     // per-LANE partial sum for the current segment run

    long long a = start;

    // Main loop: 4 atoms/iter, per-lane accumulation, reduce only on seg change.
    for (; a + 4 <= end; a += 4) {
        float4 v0 = __ldcs(&f4[(a + 0) * 32 + lane]);
        float4 v1 = __ldcs(&f4[(a + 1) * 32 + lane]);
        float4 v2 = __ldcs(&f4[(a + 2) * 32 + lane]);
        float4 v3 = __ldcs(&f4[(a + 3) * 32 + lane]);

        float s0 = fmaf(v0.x, wv.x, fmaf(v0.y, wv.y, fmaf(v0.z, wv.z, v0.w * wv.w)));
        float s1 = fmaf(v1.x, wv.x, fmaf(v1.y, wv.y, fmaf(v1.z, wv.z, v1.w * wv.w)));
        float s2 = fmaf(v2.x, wv.x, fmaf(v2.y, wv.y, fmaf(v2.z, wv.z, v2.w * wv.w)));
        float s3 = fmaf(v3.x, wv.x, fmaf(v3.y, wv.y, fmaf(v3.z, wv.z, v3.w * wv.w)));

        // seg ids for 4 consecutive atoms; start is 4-aligned so this is 16B-aligned
        int4 g = *reinterpret_cast<const int4*>(&seg[a]);

        if (g.w == cur_seg) {
            // fast path: whole quad in current segment (typical: segs avg ~100 atoms)
            acc += (s0 + s1) + (s2 + s3);
        } else {
            if (g.x != cur_seg) { flush_seg(acc, cur_seg, lane, out); cur_seg = g.x; }
            acc += s0;
            if (g.y != cur_seg) { flush_seg(acc, cur_seg, lane, out); cur_seg = g.y; }
            acc += s1;
            if (g.z != cur_seg) { flush_seg(acc, cur_seg, lane, out); cur_seg = g.z; }
            acc += s2;
            if (g.w != cur_seg) { flush_seg(acc, cur_seg, lane, out); cur_seg = g.w; }
            acc += s3;
        }
    }

    // Tail (< 4 atoms)
    for (; a < end; a++) {
        float4 v = __ldcs(&f4[a * 32 + lane]);
        float s = fmaf(v.x, wv.x, fmaf(v.y, wv.y, fmaf(v.z, wv.z, v.w * wv.w)));
        int gg = seg[a];
        if (gg != cur_seg) { flush_seg(acc, cur_seg, lane, out); cur_seg = gg; }
        acc += s;
    }

    flush_seg(acc, cur_seg, lane, out);
}

extern "C" void kernel_launch(void* const* d_in, const int* in_sizes, int n_in,
                              void* d_out, int out_size) {
    const float* f   = (const float*)d_in[0];
    const int*   seg = (const int*)d_in[1];
    const float* w   = (const float*)d_in[n_in - 1];  // w_e (128 floats) is last

    const int n_atoms = in_sizes[1];
    float* out = (float*)d_out;

    {
        int threads = 256;
        int blocks  = (out_size + threads - 1) / threads;
        zero_out_kernel<<<blocks, threads>>>(out, out_size);
    }

    const int total_warps = NUM_BLOCKS * WARPS_PER_BLOCK;
    int chunk = (n_atoms + total_warps - 1) / total_warps;
    chunk = (chunk + 3) & ~3;   // 4-aligned so int4 seg loads are aligned

    atomwise_readout_kernel<<<NUM_BLOCKS, THREADS_PER_BLOCK>>>(
        reinterpret_cast<const float4*>(f), seg, w, out, n_atoms, chunk);
}

// round 3
// speedup vs baseline: 1.0406x; 1.0172x over previous
#include <cuda_runtime.h>

#define WARPS_PER_BLOCK 8
#define THREADS_PER_BLOCK (WARPS_PER_BLOCK * 32)
#define BLOCKS_PER_SM 7
#define NUM_BLOCKS (152 * BLOCKS_PER_SM)   // GB300: 152 SMs, one exact wave

__global__ void zero_out_kernel(float* out, int n) {
    int i = blockIdx.x * blockDim.x + threadIdx.x;
    if (i < n) out[i] = 0.0f;
}

// Warp-reduce per-lane accumulator and atomically flush to out[seg_id].
__device__ __forceinline__ void flush_seg(float& acc, int seg_id, int lane,
                                          float* __restrict__ out) {
    float s = acc;
    #pragma unroll
    for (int off = 16; off > 0; off >>= 1)
        s += __shfl_xor_sync(0xFFFFFFFFu, s, off);
    if (lane == 0) atomicAdd(&out[seg_id], s);
    acc = 0.0f;
}

__launch_bounds__(THREADS_PER_BLOCK, BLOCKS_PER_SM)
__global__ void atomwise_readout_kernel(const float4* __restrict__ f4,
                                        const int* __restrict__ seg,
                                        const float* __restrict__ w,
                                        float* __restrict__ out,
                                        int n_atoms, int chunk) {
    const int lane = threadIdx.x & 31;
    const int warp_global = blockIdx.x * WARPS_PER_BLOCK + (threadIdx.x >> 5);

    long long start = (long long)warp_global * chunk;   // chunk is 4-aligned
    if (start >= n_atoms) return;
    long long end = start + chunk;
    if (end > n_atoms) end = n_atoms;

    const float4 wv = reinterpret_cast<const float4*>(w)[lane];

    int   cur_seg = seg[start];
    float acc     = 0.0f;     // per-LANE partial sum for the current segment run

    long long a = start;

    // Main loop: 4 atoms/iter. All 5 loads (4x f quad-rows + seg quad) issue
    // at the loop top before any dependent compute; seg ids sorted -> per-lane
    // accumulation, warp-reduce only on segment change.
    for (; a + 4 <= end; a += 4) {
        // seg quad first so it's in flight with the f loads (start is 4-aligned)
        int4 g = *reinterpret_cast<const int4*>(&seg[a]);

        float4 v0 = __ldcs(&f4[(a + 0) * 32 + lane]);
        float4 v1 = __ldcs(&f4[(a + 1) * 32 + lane]);
        float4 v2 = __ldcs(&f4[(a + 2) * 32 + lane]);
        float4 v3 = __ldcs(&f4[(a + 3) * 32 + lane]);

        float s0 = fmaf(v0.x, wv.x, fmaf(v0.y, wv.y, fmaf(v0.z, wv.z, v0.w * wv.w)));
        float s1 = fmaf(v1.x, wv.x, fmaf(v1.y, wv.y, fmaf(v1.z, wv.z, v1.w * wv.w)));
        float s2 = fmaf(v2.x, wv.x, fmaf(v2.y, wv.y, fmaf(v2.z, wv.z, v2.w * wv.w)));
        float s3 = fmaf(v3.x, wv.x, fmaf(v3.y, wv.y, fmaf(v3.z, wv.z, v3.w * wv.w)));

        if (g.w == cur_seg) {
            // fast path: whole quad in current segment (segs avg ~100 atoms)
            acc += (s0 + s1) + (s2 + s3);
        } else {
            if (g.x != cur_seg) { flush_seg(acc, cur_seg, lane, out); cur_seg = g.x; }
            acc += s0;
            if (g.y != cur_seg) { flush_seg(acc, cur_seg, lane, out); cur_seg = g.y; }
            acc += s1;
            if (g.z != cur_seg) { flush_seg(acc, cur_seg, lane, out); cur_seg = g.z; }
            acc += s2;
            if (g.w != cur_seg) { flush_seg(acc, cur_seg, lane, out); cur_seg = g.w; }
            acc += s3;
        }
    }

    // Tail (< 4 atoms)
    for (; a < end; a++) {
        float4 v = __ldcs(&f4[a * 32 + lane]);
        float s = fmaf(v.x, wv.x, fmaf(v.y, wv.y, fmaf(v.z, wv.z, v.w * wv.w)));
        int gg = seg[a];
        if (gg != cur_seg) { flush_seg(acc, cur_seg, lane, out); cur_seg = gg; }
        acc += s;
    }

    flush_seg(acc, cur_seg, lane, out);
}

extern "C" void kernel_launch(void* const* d_in, const int* in_sizes, int n_in,
                              void* d_out, int out_size) {
    const float* f   = (const float*)d_in[0];
    const int*   seg = (const int*)d_in[1];
    const float* w   = (const float*)d_in[n_in - 1];  // w_e (128 floats) is last

    const int n_atoms = in_sizes[1];
    float* out = (float*)d_out;

    {
        int threads = 256;
        int blocks  = (out_size + threads - 1) / threads;
        zero_out_kernel<<<blocks, threads>>>(out, out_size);
    }

    const int total_warps = NUM_BLOCKS * WARPS_PER_BLOCK;
    int chunk = (n_atoms + total_warps - 1) / total_warps;
    chunk = (chunk + 3) & ~3;   // 4-aligned so int4 seg loads are aligned

    atomwise_readout_kernel<<<NUM_BLOCKS, THREADS_PER_BLOCK>>>(
        reinterpret_cast<const float4*>(f), seg, w, out, n_atoms, chunk);
}

// round 4
// speedup vs baseline: 1.0489x; 1.0080x over previous
#include <cuda_runtime.h>

#define WARPS_PER_BLOCK 8
#define THREADS_PER_BLOCK (WARPS_PER_BLOCK * 32)
#define BLOCKS_PER_SM 8
#define NUM_BLOCKS (152 * BLOCKS_PER_SM)   // GB300: 152 SMs, one exact wave

__global__ void zero_out_kernel(float* out, int n) {
    int i = blockIdx.x * blockDim.x + threadIdx.x;
    if (i < n) out[i] = 0.0f;
}

// Warp-reduce per-lane accumulator and atomically flush to out[seg_id].
__device__ __forceinline__ void flush_seg(float& acc, int seg_id, int lane,
                                          float* __restrict__ out) {
    float s = acc;
    #pragma unroll
    for (int off = 16; off > 0; off >>= 1)
        s += __shfl_xor_sync(0xFFFFFFFFu, s, off);
    if (lane == 0) atomicAdd(&out[seg_id], s);
    acc = 0.0f;
}

__launch_bounds__(THREADS_PER_BLOCK, BLOCKS_PER_SM)
__global__ void atomwise_readout_kernel(const float4* __restrict__ f4,
                                        const int* __restrict__ seg,
                                        const float* __restrict__ w,
                                        float* __restrict__ out,
                                        int n_atoms, int chunk) {
    const int lane = threadIdx.x & 31;
    const int warp_global = blockIdx.x * WARPS_PER_BLOCK + (threadIdx.x >> 5);

    long long start = (long long)warp_global * chunk;   // chunk is 4-aligned
    if (start >= n_atoms) return;
    long long end = start + chunk;
    if (end > n_atoms) end = n_atoms;

    const float4 wv = reinterpret_cast<const float4*>(w)[lane];

    int   cur_seg = seg[start];
    float acc     = 0.0f;     // per-LANE partial sum for current segment run

    long long a = start;
    const float4* p = f4 + start * 32 + lane;

    // Main loop: 4 atoms/iter. 5 loads batched at the top; sorted seg ids ->
    // per-lane accumulation, warp-reduce only on segment change.
    for (; a + 4 <= end; a += 4, p += 128) {
        int4 g = *reinterpret_cast<const int4*>(&seg[a]);

        float4 v0 = __ldcs(p);
        float4 v1 = __ldcs(p + 32);
        float4 v2 = __ldcs(p + 64);
        float4 v3 = __ldcs(p + 96);

        float s0 = fmaf(v0.x, wv.x, fmaf(v0.y, wv.y, fmaf(v0.z, wv.z, v0.w * wv.w)));
        float s1 = fmaf(v1.x, wv.x, fmaf(v1.y, wv.y, fmaf(v1.z, wv.z, v1.w * wv.w)));
        float s2 = fmaf(v2.x, wv.x, fmaf(v2.y, wv.y, fmaf(v2.z, wv.z, v2.w * wv.w)));
        float s3 = fmaf(v3.x, wv.x, fmaf(v3.y, wv.y, fmaf(v3.z, wv.z, v3.w * wv.w)));

        if (g.w == cur_seg) {
            // fast path: whole quad in current segment (segs avg ~100 atoms)
            acc += (s0 + s1) + (s2 + s3);
        } else {
            if (g.x != cur_seg) { flush_seg(acc, cur_seg, lane, out); cur_seg = g.x; }
            acc += s0;
            if (g.y != cur_seg) { flush_seg(acc, cur_seg, lane, out); cur_seg = g.y; }
            acc += s1;
            if (g.z != cur_seg) { flush_seg(acc, cur_seg, lane, out); cur_seg = g.z; }
            acc += s2;
            if (g.w != cur_seg) { flush_seg(acc, cur_seg, lane, out); cur_seg = g.w; }
            acc += s3;
        }
    }

    // Tail (< 4 atoms)
    for (; a < end; a++, p += 32) {
        float4 v = __ldcs(p);
        float s = fmaf(v.x, wv.x, fmaf(v.y, wv.y, fmaf(v.z, wv.z, v.w * wv.w)));
        int gg = seg[a];
        if (gg != cur_seg) { flush_seg(acc, cur_seg, lane, out); cur_seg = gg; }
        acc += s;
    }

    flush_seg(acc, cur_seg, lane, out);
}

extern "C" void kernel_launch(void* const* d_in, const int* in_sizes, int n_in,
                              void* d_out, int out_size) {
    const float* f   = (const float*)d_in[0];
    const int*   seg = (const int*)d_in[1];
    const float* w   = (const float*)d_in[n_in - 1];  // w_e (128 floats) is last

    const int n_atoms = in_sizes[1];
    float* out = (float*)d_out;

    {
        int threads = 256;
        int blocks  = (out_size + threads - 1) / threads;
        zero_out_kernel<<<blocks, threads>>>(out, out_size);
    }

    const int total_warps = NUM_BLOCKS * WARPS_PER_BLOCK;
    int chunk = (n_atoms + total_warps - 1) / total_warps;
    chunk = (chunk + 3) & ~3;   // 4-aligned so int4 seg loads are aligned

    atomwise_readout_kernel<<<NUM_BLOCKS, THREADS_PER_BLOCK>>>(
        reinterpret_cast<const float4*>(f), seg, w, out, n_atoms, chunk);
}

// round 5
// speedup vs baseline: 1.0943x; 1.0433x over previous
#include <cuda_runtime.h>

#define WARPS_PER_BLOCK 8
#define THREADS_PER_BLOCK (WARPS_PER_BLOCK * 32)
#define BLOCKS_PER_SM 8
#define NUM_WAVES 4
#define NUM_BLOCKS (152 * BLOCKS_PER_SM * NUM_WAVES)  // oversubscribe: HW CTA
                                                      // streaming balances the
                                                      // per-SM speed variance

__global__ void zero_out_kernel(float* out, int n) {
    int i = blockIdx.x * blockDim.x + threadIdx.x;
    if (i < n) out[i] = 0.0f;
}

// Warp-reduce per-lane accumulator and atomically flush to out[seg_id].
__device__ __forceinline__ void flush_seg(float& acc, int seg_id, int lane,
                                          float* __restrict__ out) {
    float s = acc;
    #pragma unroll
    for (int off = 16; off > 0; off >>= 1)
        s += __shfl_xor_sync(0xFFFFFFFFu, s, off);
    if (lane == 0) atomicAdd(&out[seg_id], s);
    acc = 0.0f;
}

__launch_bounds__(THREADS_PER_BLOCK, BLOCKS_PER_SM)
__global__ void atomwise_readout_kernel(const float4* __restrict__ f4,
                                        const int* __restrict__ seg,
                                        const float* __restrict__ w,
                                        float* __restrict__ out,
                                        int n_atoms, int chunk) {
    const int lane = threadIdx.x & 31;
    const int warp_global = blockIdx.x * WARPS_PER_BLOCK + (threadIdx.x >> 5);

    long long start = (long long)warp_global * chunk;   // chunk is 4-aligned
    if (start >= n_atoms) return;
    long long end = start + chunk;
    if (end > n_atoms) end = n_atoms;

    const float4 wv = reinterpret_cast<const float4*>(w)[lane];  // L1/L2 hit

    int   cur_seg = seg[start];
    float acc     = 0.0f;     // per-LANE partial sum for current segment run

    long long a = start;
    const float4* p = f4 + start * 32 + lane;

    // Main loop: 4 atoms/iter. 5 loads batched at the top; sorted seg ids ->
    // per-lane accumulation, warp-reduce only on segment change.
    for (; a + 4 <= end; a += 4, p += 128) {
        int4 g = *reinterpret_cast<const int4*>(&seg[a]);

        float4 v0 = __ldcs(p);
        float4 v1 = __ldcs(p + 32);
        float4 v2 = __ldcs(p + 64);
        float4 v3 = __ldcs(p + 96);

        float s0 = fmaf(v0.x, wv.x, fmaf(v0.y, wv.y, fmaf(v0.z, wv.z, v0.w * wv.w)));
        float s1 = fmaf(v1.x, wv.x, fmaf(v1.y, wv.y, fmaf(v1.z, wv.z, v1.w * wv.w)));
        float s2 = fmaf(v2.x, wv.x, fmaf(v2.y, wv.y, fmaf(v2.z, wv.z, v2.w * wv.w)));
        float s3 = fmaf(v3.x, wv.x, fmaf(v3.y, wv.y, fmaf(v3.z, wv.z, v3.w * wv.w)));

        if (g.w == cur_seg) {
            // fast path: whole quad in current segment (segs avg ~100 atoms)
            acc += (s0 + s1) + (s2 + s3);
        } else {
            if (g.x != cur_seg) { flush_seg(acc, cur_seg, lane, out); cur_seg = g.x; }
            acc += s0;
            if (g.y != cur_seg) { flush_seg(acc, cur_seg, lane, out); cur_seg = g.y; }
            acc += s1;
            if (g.z != cur_seg) { flush_seg(acc, cur_seg, lane, out); cur_seg = g.z; }
            acc += s2;
            if (g.w != cur_seg) { flush_seg(acc, cur_seg, lane, out); cur_seg = g.w; }
            acc += s3;
        }
    }

    // Tail (< 4 atoms)
    for (; a < end; a++, p += 32) {
        float4 v = __ldcs(p);
        float s = fmaf(v.x, wv.x, fmaf(v.y, wv.y, fmaf(v.z, wv.z, v.w * wv.w)));
        int gg = seg[a];
        if (gg != cur_seg) { flush_seg(acc, cur_seg, lane, out); cur_seg = gg; }
        acc += s;
    }

    flush_seg(acc, cur_seg, lane, out);
}

extern "C" void kernel_launch(void* const* d_in, const int* in_sizes, int n_in,
                              void* d_out, int out_size) {
    const float* f   = (const float*)d_in[0];
    const int*   seg = (const int*)d_in[1];
    const float* w   = (const float*)d_in[n_in - 1];  // w_e (128 floats) is last

    const int n_atoms = in_sizes[1];
    float* out = (float*)d_out;

    {
        int threads = 256;
        int blocks  = (out_size + threads - 1) / threads;
        zero_out_kernel<<<blocks, threads>>>(out, out_size);
    }

    const int total_warps = NUM_BLOCKS * WARPS_PER_BLOCK;
    int chunk = (n_atoms + total_warps - 1) / total_warps;
    chunk = (chunk + 3) & ~3;   // 4-aligned so int4 seg loads are aligned

    atomwise_readout_kernel<<<NUM_BLOCKS, THREADS_PER_BLOCK>>>(
        reinterpret_cast<const float4*>(f), seg, w, out, n_atoms, chunk);
}